// round 12
// baseline (speedup 1.0000x reference)
#include <cuda_runtime.h>
#include <math.h>
#include <stdint.h>

// ---------------------------------------------------------------------------
// Matern kernel matrix via tabulated L(x) = log2(C * x^nu * K_nu(x)).
// Kernel 1: one table entry per WARP (one quadrature point per lane, shfl
// reduce) -> fully parallel prepass.
// Kernel 2: 64x64 tiles, 256 threads, 4x4 strided micro-tile, smem table,
// dot products in PACKED f32x2 FMA (fma.rn.f32x2: 1 issue slot = 2 FMAs,
// ptxas never emits it from C++) -> dot-phase issue slots halved.
// ---------------------------------------------------------------------------

#define TBL_N    1024
#define TBL_XMAX 96.0f
#define TBL_DX   (TBL_XMAX / TBL_N)
#define TBL_INVDX ((float)TBL_N / TBL_XMAX)

#define NQT 48
#define HQT (6.0f / (NQT - 1))
#define LOG2E 1.44269504088896340736f

__device__ float2 g_tbl[TBL_N + 2];   // {L_k, L_{k+1}}
__device__ float  g_fac;              // sqrt(2 nu) / lengthscale
__device__ float  g_var;              // variance

__device__ __forceinline__ float ex2f(float x) {
    float r; asm("ex2.approx.ftz.f32 %0, %1;" : "=f"(r) : "f"(x)); return r;
}
__device__ __forceinline__ float lg2f(float x) {
    float r; asm("lg2.approx.f32 %0, %1;" : "=f"(r) : "f"(x)); return r;
}
__device__ __forceinline__ float sqrt_approx(float x) {
    float r; asm("sqrt.approx.ftz.f32 %0, %1;" : "=f"(r) : "f"(x)); return r;
}
__device__ __forceinline__ void ffma2(uint64_t& d, uint64_t a, uint64_t b) {
    asm("fma.rn.f32x2 %0, %1, %2, %0;" : "+l"(d) : "l"(a), "l"(b));
}
__device__ __forceinline__ float pairsum(uint64_t p) {
    uint32_t lo, hi;
    asm("mov.b64 {%0, %1}, %2;" : "=r"(lo), "=r"(hi) : "l"(p));
    return __uint_as_float(lo) + __uint_as_float(hi);
}

// --- kernel 1: one table entry per warp --------------------------------------
__global__ __launch_bounds__(256) void build_table(const float* __restrict__ nu_p,
                                                   const float* __restrict__ lv_p,
                                                   const float* __restrict__ ll_p) {
    const int wid  = threadIdx.x >> 5;
    const int lane = threadIdx.x & 31;
    const int k    = blockIdx.x * 8 + wid;          // table index
    if (k > TBL_N) return;

    const float nu = nu_p[0];
    const float x  = TBL_DX * (float)k;

    // quadrature points q = lane and q = lane + 32 (q < 48)
    float S = 0.f;
#pragma unroll
    for (int m = 0; m < 2; m++) {
        int q = lane + 32 * m;
        if (q < NQT) {
            float t = HQT * (float)q;
            float w = (q == 0 || q == NQT - 1) ? 0.5f * HQT : HQT;
            float a = (coshf(t) - 1.f) * LOG2E;
            S += (w * coshf(nu * t)) * ex2f(-x * a);
        }
    }
    S += __shfl_xor_sync(0xffffffffu, S, 16);
    S += __shfl_xor_sync(0xffffffffu, S, 8);
    S += __shfl_xor_sync(0xffffffffu, S, 4);
    S += __shfl_xor_sync(0xffffffffu, S, 2);
    S += __shfl_xor_sync(0xffffffffu, S, 1);

    if (lane == 0) {
        float log2C = lv_p[0] * LOG2E + (1.f - nu) - lgammaf(nu) * LOG2E;
        float L = log2C + nu * lg2f(x) - x * LOG2E + lg2f(S);
        L = fmaxf(L, -150.f);
        g_tbl[k].x = L;
        if (k > 0) g_tbl[k - 1].y = L;
        if (k == 0 && blockIdx.x == 0) {
            g_fac = sqrtf(2.f * nu) * __expf(-ll_p[0]);
            g_var = __expf(lv_p[0]);
        }
    }
}

// --- kernel 2: 64x64 tiles, 4x4 strided micro, f32x2 dot, smem table ---------
__global__ __launch_bounds__(256) void matern_main(const float* __restrict__ X,
                                                   float* __restrict__ out,
                                                   int N) {
    __shared__ float  sxi[64][36];
    __shared__ float  sxj[64][36];
    __shared__ float  sni[64], snj[64];
    __shared__ float2 stbl[TBL_N + 1];

    const int tid = threadIdx.x;
    const int tx = tid & 15, ty = tid >> 4;
    const int i0 = blockIdx.y * 64, j0 = blockIdx.x * 64;

    // table copy FIRST (coalesced LDG.128; overlaps with tile loads below)
    {
        const float4* gt = (const float4*)g_tbl;   // 1025 float2 = 512.5 float4
#pragma unroll
        for (int m = 0; m < 2; m++) {
            int idx = m * 256 + tid;               // 0..511
            *(float4*)&stbl[idx * 2] = gt[idx];
        }
        if (tid == 0) stbl[TBL_N] = g_tbl[TBL_N];
    }

    const float scale = g_fac * TBL_INVDX;   // uniform broadcast

    // tile loads + scale + fused norm reduction (8 lanes per row)
    {
        const float4* Xi = (const float4*)(X + i0 * 32);
        const float4* Xj = (const float4*)(X + j0 * 32);
        const int k = tid & 7;
#pragma unroll
        for (int m = 0; m < 2; m++) {
            int idx = m * 256 + tid;          // 0..511
            int r = idx >> 3;
            float4 vi = Xi[idx];
            float4 vj = Xj[idx];
            vi.x *= scale; vi.y *= scale; vi.z *= scale; vi.w *= scale;
            vj.x *= scale; vj.y *= scale; vj.z *= scale; vj.w *= scale;
            *(float4*)&sxi[r][4 * k] = vi;
            *(float4*)&sxj[r][4 * k] = vj;
            float pi = fmaf(vi.x, vi.x, fmaf(vi.y, vi.y, fmaf(vi.z, vi.z, vi.w * vi.w)));
            float pj = fmaf(vj.x, vj.x, fmaf(vj.y, vj.y, fmaf(vj.z, vj.z, vj.w * vj.w)));
            pi += __shfl_xor_sync(0xffffffffu, pi, 1);
            pj += __shfl_xor_sync(0xffffffffu, pj, 1);
            pi += __shfl_xor_sync(0xffffffffu, pi, 2);
            pj += __shfl_xor_sync(0xffffffffu, pj, 2);
            pi += __shfl_xor_sync(0xffffffffu, pi, 4);
            pj += __shfl_xor_sync(0xffffffffu, pj, 4);
            if (k == 0) { sni[r] = pi; snj[r] = pj; }
        }
    }
    __syncthreads();

    // 4x4 micro-tile dot in packed f32x2: rows i = ty*4 + r, cols j = tx + 16*c
    uint64_t acc2[4][4];
#pragma unroll
    for (int r = 0; r < 4; r++)
#pragma unroll
        for (int c = 0; c < 4; c++) acc2[r][c] = 0ull;

#pragma unroll
    for (int kc = 0; kc < 8; kc++) {
        ulonglong2 a2[4], b2[4];
#pragma unroll
        for (int r = 0; r < 4; r++)
            a2[r] = *(const ulonglong2*)&sxi[ty * 4 + r][kc * 4];
#pragma unroll
        for (int c = 0; c < 4; c++)
            b2[c] = *(const ulonglong2*)&sxj[tx + 16 * c][kc * 4];
#pragma unroll
        for (int r = 0; r < 4; r++)
#pragma unroll
            for (int c = 0; c < 4; c++) {
                ffma2(acc2[r][c], a2[r].x, b2[c].x);
                ffma2(acc2[r][c], a2[r].y, b2[c].y);
            }
    }

    const float var_s = g_var;
    float ni[4], nj[4];
#pragma unroll
    for (int r = 0; r < 4; r++) ni[r] = sni[ty * 4 + r];
#pragma unroll
    for (int c = 0; c < 4; c++) nj[c] = snj[tx + 16 * c];

    const bool diagblk = (blockIdx.x == blockIdx.y);

#pragma unroll
    for (int r = 0; r < 4; r++) {
        const int i = i0 + ty * 4 + r;
#pragma unroll
        for (int c = 0; c < 4; c++) {
            const int j = j0 + tx + 16 * c;
            float dot = pairsum(acc2[r][c]);
            float sq = fmaxf(fmaf(-2.f, dot, ni[r] + nj[c]), 0.f);
            float u  = fminf(sqrt_approx(sq), (float)TBL_N - 0.001f);
            int   kk = (int)u;
            float f  = u - (float)kk;
            float2 Lp = stbl[kk];
            float val = ex2f(fmaf(f, Lp.y - Lp.x, Lp.x));
            if (diagblk && i == j) val = var_s;
            out[i * N + j] = val;
        }
    }
}

extern "C" void kernel_launch(void* const* d_in, const int* in_sizes, int n_in,
                              void* d_out, int out_size) {
    const float* X  = (const float*)d_in[0];
    const float* nu = (const float*)d_in[1];
    const float* lv = (const float*)d_in[2];
    const float* ll = (const float*)d_in[3];
    float* out = (float*)d_out;
    const int N = in_sizes[0] / 32;   // 1024

    build_table<<<(TBL_N + 1 + 7) / 8, 256>>>(nu, lv, ll);

    dim3 grid(N / 64, N / 64), block(256);
    matern_main<<<grid, block>>>(X, out, N);
}

// round 13
// speedup vs baseline: 1.2657x; 1.2657x over previous
#include <cuda_runtime.h>
#include <math.h>

// ---------------------------------------------------------------------------
// Matern kernel matrix, SINGLE fused kernel (two-kernel graphs cost ~2.5us of
// node overhead vs 0.8us for one).
// Each block builds its own 257-entry table L(x) = log2(C x^nu K_nu(x)) over
// x in [0,48] (du=0.1875, one entry per thread, 32-pt trapezoid of the
// reference's integral -- spectrally exact in the data range x<=31), fully
// overlapped with the tile-load LDG latency. 64x64 tiles, 256 threads,
// 4x4 strided micro-tile (conflict-free LDS), tiles pre-scaled by fac/du so
// sqrt.approx yields the table coordinate directly.
// ---------------------------------------------------------------------------

#define NQ2 32
#define HQ2 (6.0f / (NQ2 - 1))
#define DU     (48.0f / 256.0f)
#define INV_DU (256.0f / 48.0f)
#define LOG2E 1.44269504088896340736f

__device__ __forceinline__ float ex2f(float x) {
    float r; asm("ex2.approx.ftz.f32 %0, %1;" : "=f"(r) : "f"(x)); return r;
}
__device__ __forceinline__ float lg2f(float x) {
    float r; asm("lg2.approx.f32 %0, %1;" : "=f"(r) : "f"(x)); return r;
}
__device__ __forceinline__ float sqrt_approx(float x) {
    float r; asm("sqrt.approx.ftz.f32 %0, %1;" : "=f"(r) : "f"(x)); return r;
}

__global__ __launch_bounds__(256) void matern_fused(const float* __restrict__ X,
                                                    const float* __restrict__ nu_p,
                                                    const float* __restrict__ lv_p,
                                                    const float* __restrict__ ll_p,
                                                    float* __restrict__ out,
                                                    int N) {
    __shared__ float sxi[64][36];
    __shared__ float sxj[64][36];
    __shared__ float sni[64], snj[64];
    __shared__ float s_a[NQ2];     // (cosh t_q - 1) * log2(e)
    __shared__ float s_c[NQ2];     // w_q * cosh(nu t_q)
    __shared__ float stbl[257];    // L(k * DU)
    __shared__ float s_scale, s_var, s_log2C, s_nu;

    const int tid = threadIdx.x;
    const int tx = tid & 15, ty = tid >> 4;
    const int i0 = blockIdx.y * 64, j0 = blockIdx.x * 64;

    // issue tile LDGs early (latency overlapped with coefficient/scalar math)
    const float4* Xi = (const float4*)(X + i0 * 32);
    const float4* Xj = (const float4*)(X + j0 * 32);
    float4 vi0 = Xi[tid], vj0 = Xj[tid];
    float4 vi1 = Xi[256 + tid], vj1 = Xj[256 + tid];

    // quadrature coefficients + scalar constants
    if (tid < NQ2) {
        float nu = nu_p[0];
        float t  = HQ2 * (float)tid;
        s_a[tid] = (coshf(t) - 1.f) * LOG2E;
        float w  = (tid == 0 || tid == NQ2 - 1) ? 0.5f * HQ2 : HQ2;
        s_c[tid] = w * coshf(nu * t);
    } else if (tid == 32) {
        float nu = nu_p[0], lv = lv_p[0], ll = ll_p[0];
        s_scale = sqrtf(2.f * nu) * __expf(-ll) * INV_DU;
        s_var   = __expf(lv);
        s_log2C = lv * LOG2E + (1.f - nu) - lgammaf(nu) * LOG2E;
        s_nu    = nu;
    }
    __syncthreads();

    const float scale = s_scale;

    // tiles (prescaled) + fused norm reduction (8 lanes per row)
    {
        const int k = tid & 7;
        float4 vv[2][2] = {{vi0, vj0}, {vi1, vj1}};
#pragma unroll
        for (int m = 0; m < 2; m++) {
            int idx = m * 256 + tid;
            int r = idx >> 3;
            float4 vi = vv[m][0], vj = vv[m][1];
            vi.x *= scale; vi.y *= scale; vi.z *= scale; vi.w *= scale;
            vj.x *= scale; vj.y *= scale; vj.z *= scale; vj.w *= scale;
            *(float4*)&sxi[r][4 * k] = vi;
            *(float4*)&sxj[r][4 * k] = vj;
            float pi = fmaf(vi.x, vi.x, fmaf(vi.y, vi.y, fmaf(vi.z, vi.z, vi.w * vi.w)));
            float pj = fmaf(vj.x, vj.x, fmaf(vj.y, vj.y, fmaf(vj.z, vj.z, vj.w * vj.w)));
            pi += __shfl_xor_sync(0xffffffffu, pi, 1);
            pj += __shfl_xor_sync(0xffffffffu, pj, 1);
            pi += __shfl_xor_sync(0xffffffffu, pi, 2);
            pj += __shfl_xor_sync(0xffffffffu, pj, 2);
            pi += __shfl_xor_sync(0xffffffffu, pi, 4);
            pj += __shfl_xor_sync(0xffffffffu, pj, 4);
            if (k == 0) { sni[r] = pi; snj[r] = pj; }
        }
    }

    // per-thread table entry: L(x_k), k = tid  (entry 256 never read: u<=254.99)
    {
        const float x = DU * (float)tid;
        float S = 0.f;
#pragma unroll
        for (int q = 0; q < NQ2; q++) {
            S = fmaf(s_c[q], ex2f(-x * s_a[q]), S);
        }
        float L = s_log2C + s_nu * lg2f(x) - x * LOG2E + lg2f(S);
        stbl[tid] = fmaxf(L, -150.f);
    }
    __syncthreads();

    // 4x4 micro-tile dot: rows i = ty*4 + r (contiguous), cols j = tx + 16*c
    float acc[4][4];
#pragma unroll
    for (int r = 0; r < 4; r++)
#pragma unroll
        for (int c = 0; c < 4; c++) acc[r][c] = 0.f;

#pragma unroll
    for (int kc = 0; kc < 8; kc++) {
        float4 a[4], b[4];
#pragma unroll
        for (int r = 0; r < 4; r++) a[r] = *(const float4*)&sxi[ty * 4 + r][kc * 4];
#pragma unroll
        for (int c = 0; c < 4; c++) b[c] = *(const float4*)&sxj[tx + 16 * c][kc * 4];
#pragma unroll
        for (int r = 0; r < 4; r++)
#pragma unroll
            for (int c = 0; c < 4; c++) {
                acc[r][c] = fmaf(a[r].x, b[c].x, acc[r][c]);
                acc[r][c] = fmaf(a[r].y, b[c].y, acc[r][c]);
                acc[r][c] = fmaf(a[r].z, b[c].z, acc[r][c]);
                acc[r][c] = fmaf(a[r].w, b[c].w, acc[r][c]);
            }
    }

    const float var_s = s_var;
    float ni[4], nj[4];
#pragma unroll
    for (int r = 0; r < 4; r++) ni[r] = sni[ty * 4 + r];
#pragma unroll
    for (int c = 0; c < 4; c++) nj[c] = snj[tx + 16 * c];

    const bool diagblk = (blockIdx.x == blockIdx.y);

#pragma unroll
    for (int r = 0; r < 4; r++) {
        const int i = i0 + ty * 4 + r;
#pragma unroll
        for (int c = 0; c < 4; c++) {
            const int j = j0 + tx + 16 * c;
            float sq = fmaxf(fmaf(-2.f, acc[r][c], ni[r] + nj[c]), 0.f);
            float u  = fminf(sqrt_approx(sq), 254.99f);
            int   kk = (int)u;
            float f  = u - (float)kk;
            float L0 = stbl[kk], L1 = stbl[kk + 1];
            float val = ex2f(fmaf(f, L1 - L0, L0));
            if (diagblk && i == j) val = var_s;
            out[i * N + j] = val;
        }
    }
}

extern "C" void kernel_launch(void* const* d_in, const int* in_sizes, int n_in,
                              void* d_out, int out_size) {
    const float* X  = (const float*)d_in[0];
    const float* nu = (const float*)d_in[1];
    const float* lv = (const float*)d_in[2];
    const float* ll = (const float*)d_in[3];
    float* out = (float*)d_out;
    const int N = in_sizes[0] / 32;   // 1024

    dim3 grid(N / 64, N / 64), block(256);
    matern_fused<<<grid, block>>>(X, nu, lv, ll, out, N);
}